// round 11
// baseline (speedup 1.0000x reference)
#include <cuda_runtime.h>
#include <cstdint>

// Inv1x1MM_SVD, C=16, 65536 positions.
// ROW-SLAB layout, 2 lanes per position: lane (pos, half) holds rows
// half*8..half*8+7 of the 16x16 working matrix, packed f32x2 column pairs.
// vs R10: w[] lives in shared memory during the V QR (16 fewer live regs at
// the pressure peak) and __launch_bounds__(64,7) locks 7 blocks/SM.
// One smem buffer per position serves as rs (U phase) then w (V phase).

constexpr int NPOS = 8 * 8192;

#define FMA2(d, a, b, c) asm("fma.rn.f32x2 %0, %1, %2, %3;" : "=l"(d) : "l"(a), "l"(b), "l"(c))
#define MUL2(d, a, b)    asm("mul.rn.f32x2 %0, %1, %2;"     : "=l"(d) : "l"(a), "l"(b))
#define ADD2(d, a, b)    asm("add.rn.f32x2 %0, %1, %2;"     : "=l"(d) : "l"(a), "l"(b))
#define PACK2(d, lo, hi) asm("mov.b64 %0, {%1, %2};"        : "=l"(d) : "f"(lo), "f"(hi))
#define UNPACK2(lo, hi, d) asm("mov.b64 {%0, %1}, %2;" : "=f"(lo), "=f"(hi) : "l"(d))

__device__ __forceinline__ uint64_t shx1(uint64_t v) {
    uint32_t lo, hi;
    asm("mov.b64 {%0, %1}, %2;" : "=r"(lo), "=r"(hi) : "l"(v));
    lo = __shfl_xor_sync(0xffffffffu, lo, 1);
    hi = __shfl_xor_sync(0xffffffffu, hi, 1);
    uint64_t r;
    asm("mov.b64 %0, {%1, %2};" : "=l"(r) : "r"(lo), "r"(hi));
    return r;
}
__device__ __forceinline__ float frcp(float x) {
    float r;
    asm("rcp.approx.f32 %0, %1;" : "=f"(r) : "f"(x));
    return r;
}

// MGS, rows split across a lane pair.
// SCALEW=false: writer lane STORES 1/||b_k|| to sm[k]   (rs phase).
// SCALEW=true : writer lane FOLDS 1/||b_k|| into sm[k]  (w phase).
template <bool SCALEW>
__device__ __forceinline__ void mgs2(uint64_t (&A)[8][8], float* sm, bool writer) {
    #pragma unroll
    for (int k = 0; k < 15; k++) {
        const int c0 = k >> 1;
        const int cu = (k + 1) >> 1;

        uint64_t ak[8];
        #pragma unroll
        for (int i = 0; i < 8; i++) {
            float lo, hi;
            UNPACK2(lo, hi, A[i][c0]);
            const float x = (k & 1) ? hi : lo;
            PACK2(ak[i], x, x);
        }

        uint64_t pp[8];
        #pragma unroll
        for (int c = c0; c < 8; c++) {
            uint64_t s0, s1;
            MUL2(s0, ak[0], A[0][c]);
            MUL2(s1, ak[4], A[4][c]);
            FMA2(s0, ak[1], A[1][c], s0);
            FMA2(s1, ak[5], A[5][c], s1);
            FMA2(s0, ak[2], A[2][c], s0);
            FMA2(s1, ak[6], A[6][c], s1);
            FMA2(s0, ak[3], A[3][c], s0);
            FMA2(s1, ak[7], A[7][c], s1);
            ADD2(s0, s0, s1);
            const uint64_t o = shx1(s0);
            ADD2(pp[c], s0, o);
        }

        float plo, phi;
        UNPACK2(plo, phi, pp[c0]);
        const float pk = fmaxf((k & 1) ? phi : plo, 1e-30f);
        const float ninv = -frcp(pk);        // projection path (MUFU.RCP)
        const float r = rsqrtf(pk);          // normalization path (parallel MUFU.RSQ)
        if (writer) {
            if (SCALEW) sm[k] *= r; else sm[k] = r;
        }
        uint64_t n2;
        PACK2(n2, ninv, ninv);

        #pragma unroll
        for (int c = cu; c < 8; c++) {
            uint64_t s;
            MUL2(s, pp[c], n2);
            if (!(k & 1) && c == cu) {       // pair contains j == k: mask lo half
                float sl, sh;
                UNPACK2(sl, sh, s);
                PACK2(s, 0.0f, sh);
            }
            #pragma unroll
            for (int i = 0; i < 8; i++) FMA2(A[i][c], s, ak[i], A[i][c]);
        }
    }
    // column 15 norm
    float n15 = 0.0f;
    #pragma unroll
    for (int i = 0; i < 8; i++) {
        float lo, hi;
        UNPACK2(lo, hi, A[i][7]);
        n15 = fmaf(hi, hi, n15);
    }
    n15 += __shfl_xor_sync(0xffffffffu, n15, 1);
    const float r = rsqrtf(fmaxf(n15, 1e-30f));
    if (writer) {
        if (SCALEW) sm[15] *= r; else sm[15] = r;
    }
}

__device__ __forceinline__ void load_mat(uint64_t (&A)[8][8], const float4* f4, int rbase) {
    #pragma unroll
    for (int i = 0; i < 8; i++) {
        const float4 q0 = __ldg(&f4[rbase + 4 * i + 0]);
        const float4 q1 = __ldg(&f4[rbase + 4 * i + 1]);
        const float4 q2 = __ldg(&f4[rbase + 4 * i + 2]);
        const float4 q3 = __ldg(&f4[rbase + 4 * i + 3]);
        PACK2(A[i][0], q0.x, q0.y); PACK2(A[i][1], q0.z, q0.w);
        PACK2(A[i][2], q1.x, q1.y); PACK2(A[i][3], q1.z, q1.w);
        PACK2(A[i][4], q2.x, q2.y); PACK2(A[i][5], q2.z, q2.w);
        PACK2(A[i][6], q3.x, q3.y); PACK2(A[i][7], q3.z, q3.w);
    }
}

__global__ void __launch_bounds__(64, 7)
inv1x1mm_svd_kernel(const float* __restrict__ data,
                    const float* __restrict__ paras,
                    float* __restrict__ out) {
    // stride 18 floats (72 B): 8-byte aligned rows for v2 access, distinct
    // bank pairs across the 16 positions of a warp.
    __shared__ __align__(8) float sm[32][18];

    const int tid  = threadIdx.x;
    const int half = tid & 1;
    const int p    = tid >> 1;
    const int pos  = blockIdx.x * 32 + p;

    const float4* f4 = (const float4*)(paras + (size_t)pos * 528);
    float* smrow = &sm[p][0];
    const bool writer = (half == 0);

    uint64_t A[8][8];

    // ===== QR of U =====  (writes rs into smrow)
    load_mat(A, f4, 4 + half * 32);
    mgs2<false>(A, smrow, writer);

    // local partial dots v_j against U's Q (before A is reloaded with V)
    const float4 d0 = __ldg((const float4*)(data + pos * 16 + half * 8));
    const float4 d1 = __ldg((const float4*)(data + pos * 16 + half * 8 + 4));
    uint64_t dd[8];
    PACK2(dd[0], d0.x, d0.x); PACK2(dd[1], d0.y, d0.y);
    PACK2(dd[2], d0.z, d0.z); PACK2(dd[3], d0.w, d0.w);
    PACK2(dd[4], d1.x, d1.x); PACK2(dd[5], d1.y, d1.y);
    PACK2(dd[6], d1.z, d1.z); PACK2(dd[7], d1.w, d1.w);

    uint64_t w[8];
    #pragma unroll
    for (int c = 0; c < 8; c++) {
        uint64_t s0, s1;
        MUL2(s0, dd[0], A[0][c]);
        MUL2(s1, dd[4], A[4][c]);
        FMA2(s0, dd[1], A[1][c], s0);
        FMA2(s1, dd[5], A[5][c], s1);
        FMA2(s0, dd[2], A[2][c], s0);
        FMA2(s1, dd[6], A[6][c], s1);
        FMA2(s0, dd[3], A[3][c], s0);
        FMA2(s1, dd[7], A[7][c], s1);
        ADD2(w[c], s0, s1);
    }

    // reload A with V now; the reduce/exp below hides the LDG latency
    load_mat(A, f4, 68 + half * 32);

    __syncwarp();   // partner's rs writes -> my reads
    #pragma unroll
    for (int c = 0; c < 8; c++) {
        const uint64_t o = shx1(w[c]);
        ADD2(w[c], w[c], o);
        const float2 lsp = __ldg((const float2*)(paras + (size_t)pos * 528 + 2 * c));
        const float2 rsp = *(const float2*)&smrow[2 * c];   // rs pair (v2 lds)
        uint64_t m;
        PACK2(m, __expf(lsp.x) * rsp.x, __expf(lsp.y) * rsp.y);
        MUL2(w[c], w[c], m);
        // store w into the SAME smem slot (read-before-write, warp-converged)
        if (writer) {
            float wl, wh;
            UNPACK2(wl, wh, w[c]);
            *(float2*)&smrow[2 * c] = make_float2(wl, wh);
        }
    }

    // ===== QR of V =====  (folds 1/||b1_j|| into smem w; w regs are dead)
    mgs2<true>(A, smrow, writer);
    __syncwarp();   // writer's w folds -> both lanes' epilogue reads

    // res_d = sum_j w_j * b1[d][j]  (d = my 8 local rows)
    uint64_t ww[8];
    #pragma unroll
    for (int c = 0; c < 8; c++) {
        const float2 t = *(const float2*)&smrow[2 * c];
        PACK2(ww[c], t.x, t.y);
    }
    float o[8];
    #pragma unroll
    for (int i = 0; i < 8; i++) {
        uint64_t s0, s1;
        MUL2(s0, ww[0], A[i][0]);
        MUL2(s1, ww[4], A[i][4]);
        FMA2(s0, ww[1], A[i][1], s0);
        FMA2(s1, ww[5], A[i][5], s1);
        FMA2(s0, ww[2], A[i][2], s0);
        FMA2(s1, ww[6], A[i][6], s1);
        FMA2(s0, ww[3], A[i][3], s0);
        FMA2(s1, ww[7], A[i][7], s1);
        ADD2(s0, s0, s1);
        float lo, hi;
        UNPACK2(lo, hi, s0);
        o[i] = lo + hi;
    }

    float4* o4 = (float4*)(out + pos * 16 + half * 8);
    o4[0] = make_float4(o[0], o[1], o[2], o[3]);
    o4[1] = make_float4(o[4], o[5], o[6], o[7]);
}

extern "C" void kernel_launch(void* const* d_in, const int* in_sizes, int n_in,
                              void* d_out, int out_size) {
    const float* data  = (const float*)d_in[0];
    const float* paras = (const float*)d_in[1];
    if (n_in >= 2 && in_sizes[0] > in_sizes[1]) {  // defensive ordering by size
        data  = (const float*)d_in[1];
        paras = (const float*)d_in[0];
    }
    inv1x1mm_svd_kernel<<<NPOS / 32, 64>>>(data, paras, (float*)d_out);
}